// round 3
// baseline (speedup 1.0000x reference)
#include <cuda_runtime.h>
#include <math.h>

#define BATCH 4
#define T_IN 1920
#define E_IN 512
#define C1 128
#define T1 640
#define C2 1024
#define T2 128

// Scratch (device globals; allocations forbidden)
__device__ float  g_h1[5 * T1 * C1];            // conv1+ln1+silu output (4 batches + symbols)
__device__ float  g_c2raw[5 * T2 * C2];         // conv2 pre-LN output
__device__ float  g_vp[BATCH * T2 * C2];        // values_projected
__device__ float  g_sp[T2 * C2];                // symbol_projected
__device__ float  g_S4[4 * BATCH * T2 * T2];    // similarity partials per d-chunk
__device__ float2 g_wpk1[5 * 256 * 128];        // conv1 w repacked: (k,c2,o) -> (w[2c2][o], w[2c2+1][o])
__device__ float2 g_wpk2[3 * 64 * 1024];        // conv2 w repacked

__device__ __forceinline__ float silu_f(float y) { return y / (1.0f + expf(-y)); }

__device__ __forceinline__ unsigned long long fma2(unsigned long long a,
                                                   unsigned long long b,
                                                   unsigned long long c) {
    unsigned long long d;
    asm("fma.rn.f32x2 %0, %1, %2, %3;" : "=l"(d) : "l"(a), "l"(b), "l"(c));
    return d;
}
__device__ __forceinline__ float pksum(unsigned long long p) {
    unsigned int lo, hi;
    asm("mov.b64 {%0, %1}, %2;" : "=r"(lo), "=r"(hi) : "l"(p));
    return __uint_as_float(lo) + __uint_as_float(hi);
}

// ---------------------------------------------------------------------------
// Kernel 0: repack conv weights into c-pair (f32x2) layout
// ---------------------------------------------------------------------------
__global__ void prepack(const float* __restrict__ w1, const float* __restrict__ w2) {
    int idx = blockIdx.x * 256 + threadIdx.x;
    if (idx < 5 * 256 * 128) {
        int o  = idx & 127;
        int c2 = (idx >> 7) & 255;
        int k  = idx >> 15;
        const float* p = w1 + ((size_t)(k * 512 + 2 * c2)) * 128 + o;
        g_wpk1[idx] = make_float2(p[0], p[128]);
    }
    if (idx < 3 * 64 * 1024) {
        int o  = idx & 1023;
        int c2 = (idx >> 10) & 63;
        int k  = idx >> 16;
        const float* p = w2 + ((size_t)(k * 128 + 2 * c2)) * 1024 + o;
        g_wpk2[idx] = make_float2(p[0], p[1024]);
    }
}

// ---------------------------------------------------------------------------
// Kernel A: conv1 (stride 3, win 5, pad 1/1) + layernorm(128) + silu
// 200 blocks x 256 threads; warp owns 2 timesteps, lane owns 4 channels.
// Prepacked weights: no pack movs in the hot loop.
// ---------------------------------------------------------------------------
#define TS1 16
#define ECH1 128
#define ROWS1 (3 * (TS1 - 1) + 5)   // 50

__global__ void conv1_ln_silu(const float* __restrict__ values,
                              const float* __restrict__ symbols,
                              const float* __restrict__ bias,
                              const float* __restrict__ lng,
                              const float* __restrict__ lnb) {
    __shared__ float xs[ROWS1 * ECH1];   // 25.6KB

    int blk = blockIdx.x;
    int src, t0;
    if (blk < 160) { src = blk / 40; t0 = (blk % 40) * TS1; }
    else           { src = 4;        t0 = (blk - 160) * TS1; }
    const float* x = (src < 4) ? (values + (size_t)src * T_IN * E_IN) : symbols;

    int base_row = t0 * 3 - 1;
    int t    = threadIdx.x;
    int lane = t & 31;
    int wrp  = t >> 5;
    int ch0  = lane * 4;
    int j0   = wrp * 2;

    unsigned long long acc[2][4];
#pragma unroll
    for (int jj = 0; jj < 2; jj++)
#pragma unroll
        for (int q = 0; q < 4; q++) acc[jj][q] = 0ULL;

    for (int cc = 0; cc < E_IN; cc += ECH1) {
        __syncthreads();
        for (int idx = t; idx < ROWS1 * (ECH1 / 4); idx += 256) {
            int r  = idx >> 5;
            int c4 = idx & 31;
            int gr = base_row + r;
            float4 v = make_float4(0.f, 0.f, 0.f, 0.f);
            if (gr >= 0 && gr < T_IN)
                v = ((const float4*)(x + (size_t)gr * E_IN + cc))[c4];
            ((float4*)xs)[idx] = v;
        }
        __syncthreads();

#pragma unroll
        for (int k = 0; k < 5; k++) {
            const float2* wrow = g_wpk1 + ((size_t)(k * 256 + (cc >> 1))) * 128 + ch0;
            const unsigned long long* xp0 =
                (const unsigned long long*)&xs[(3 * j0 + k) * ECH1];
            const unsigned long long* xp1 =
                (const unsigned long long*)&xs[(3 * (j0 + 1) + k) * ECH1];
            for (int c2 = 0; c2 < ECH1 / 2; c2 += 2) {
                const float2* wq = wrow + (size_t)c2 * 128;
                ulonglong2 wA = *(const ulonglong2*)(wq);          // ch0, ch0+1 @ c2
                ulonglong2 wB = *(const ulonglong2*)(wq + 2);      // ch0+2, ch0+3 @ c2
                ulonglong2 wC = *(const ulonglong2*)(wq + 128);    // ch0, ch0+1 @ c2+1
                ulonglong2 wD = *(const ulonglong2*)(wq + 130);    // ch0+2, ch0+3 @ c2+1

                ulonglong2 x0 = *(const ulonglong2*)(xp0 + c2);
                acc[0][0] = fma2(x0.x, wA.x, acc[0][0]);
                acc[0][1] = fma2(x0.x, wA.y, acc[0][1]);
                acc[0][2] = fma2(x0.x, wB.x, acc[0][2]);
                acc[0][3] = fma2(x0.x, wB.y, acc[0][3]);
                acc[0][0] = fma2(x0.y, wC.x, acc[0][0]);
                acc[0][1] = fma2(x0.y, wC.y, acc[0][1]);
                acc[0][2] = fma2(x0.y, wD.x, acc[0][2]);
                acc[0][3] = fma2(x0.y, wD.y, acc[0][3]);

                ulonglong2 x1 = *(const ulonglong2*)(xp1 + c2);
                acc[1][0] = fma2(x1.x, wA.x, acc[1][0]);
                acc[1][1] = fma2(x1.x, wA.y, acc[1][1]);
                acc[1][2] = fma2(x1.x, wB.x, acc[1][2]);
                acc[1][3] = fma2(x1.x, wB.y, acc[1][3]);
                acc[1][0] = fma2(x1.y, wC.x, acc[1][0]);
                acc[1][1] = fma2(x1.y, wC.y, acc[1][1]);
                acc[1][2] = fma2(x1.y, wD.x, acc[1][2]);
                acc[1][3] = fma2(x1.y, wD.y, acc[1][3]);
            }
        }
    }

    float bv[4], gg[4], bb[4];
#pragma unroll
    for (int q = 0; q < 4; q++) {
        bv[q] = bias[ch0 + q]; gg[q] = lng[ch0 + q]; bb[q] = lnb[ch0 + q];
    }

#pragma unroll
    for (int jj = 0; jj < 2; jj++) {
        float v[4], s = 0.f, s2 = 0.f;
#pragma unroll
        for (int q = 0; q < 4; q++) {
            v[q] = pksum(acc[jj][q]) + bv[q];
            s += v[q]; s2 += v[q] * v[q];
        }
#pragma unroll
        for (int off = 16; off; off >>= 1) {
            s  += __shfl_xor_sync(0xffffffffu, s,  off);
            s2 += __shfl_xor_sync(0xffffffffu, s2, off);
        }
        float m   = s * (1.0f / C1);
        float var = s2 * (1.0f / C1) - m * m;
        float rs  = rsqrtf(var + 1e-3f);
        float4 o4;
        o4.x = silu_f((v[0] - m) * rs * gg[0] + bb[0]);
        o4.y = silu_f((v[1] - m) * rs * gg[1] + bb[1]);
        o4.z = silu_f((v[2] - m) * rs * gg[2] + bb[2]);
        o4.w = silu_f((v[3] - m) * rs * gg[3] + bb[3]);
        *(float4*)&g_h1[((size_t)src * T1 + (t0 + j0 + jj)) * C1 + ch0] = o4;
    }
}

// ---------------------------------------------------------------------------
// Kernel B1: conv2 raw (stride 5, win 3), channel-halved for 160 blocks.
// 256 threads; thread owns 2 adjacent channels x 8 timesteps.
// ---------------------------------------------------------------------------
#define TS2 8
#define ROWS2 (5 * (TS2 - 1) + 3)   // 38

__global__ void conv2_raw(const float* __restrict__ bias) {
    __shared__ float xs[ROWS2 * C1];   // 19KB

    int blk = blockIdx.x;                 // 160 = 5 src * 16 tg * 2 chh
    int src = blk / 32;
    int rem = blk % 32;
    int tg  = rem >> 1;
    int chh = rem & 1;
    int t0  = tg * TS2;
    const float* x = g_h1 + (size_t)src * T1 * C1;
    int base_row = t0 * 5;

    int t   = threadIdx.x;
    int ch0 = chh * 512 + t * 2;

    for (int idx = t; idx < ROWS2 * (C1 / 4); idx += 256) {
        int r = idx >> 5, c4 = idx & 31;
        ((float4*)xs)[idx] = ((const float4*)(x + (size_t)(base_row + r) * C1))[c4];
    }
    __syncthreads();

    unsigned long long acc[TS2][2];
#pragma unroll
    for (int j = 0; j < TS2; j++) { acc[j][0] = 0ULL; acc[j][1] = 0ULL; }

#pragma unroll
    for (int k = 0; k < 3; k++) {
        const float2* wrow = g_wpk2 + (size_t)(k * 64) * 1024 + ch0;
#pragma unroll 2
        for (int c2 = 0; c2 < 64; c2++) {
            ulonglong2 wv = *(const ulonglong2*)(wrow + (size_t)c2 * 1024);
#pragma unroll
            for (int j = 0; j < TS2; j++) {
                unsigned long long xv =
                    *(const unsigned long long*)&xs[(5 * j + k) * C1 + 2 * c2];
                acc[j][0] = fma2(xv, wv.x, acc[j][0]);
                acc[j][1] = fma2(xv, wv.y, acc[j][1]);
            }
        }
    }

    float b0 = bias[ch0], b1 = bias[ch0 + 1];
#pragma unroll
    for (int j = 0; j < TS2; j++) {
        float2 o2 = make_float2(pksum(acc[j][0]) + b0, pksum(acc[j][1]) + b1);
        *(float2*)&g_c2raw[((size_t)(src * T2 + t0 + j)) * C2 + ch0] = o2;
    }
}

// ---------------------------------------------------------------------------
// Kernel B2: layernorm(1024) + silu over conv2 output.
// 640 blocks (one row each) x 256 threads (float4 per thread).
// ---------------------------------------------------------------------------
__global__ void ln2_silu(const float* __restrict__ lng,
                         const float* __restrict__ lnb,
                         float* __restrict__ out_vp_copy) {
    __shared__ float red[2][8];
    int row = blockIdx.x;           // 0..639
    int src = row >> 7;
    int t = threadIdx.x, lane = t & 31, wid = t >> 5;
    int ch = 4 * t;

    float4 v = *(const float4*)&g_c2raw[(size_t)row * C2 + ch];
    float s  = v.x + v.y + v.z + v.w;
    float s2 = v.x * v.x + v.y * v.y + v.z * v.z + v.w * v.w;
#pragma unroll
    for (int off = 16; off; off >>= 1) {
        s  += __shfl_xor_sync(0xffffffffu, s,  off);
        s2 += __shfl_xor_sync(0xffffffffu, s2, off);
    }
    if (lane == 0) { red[0][wid] = s; red[1][wid] = s2; }
    __syncthreads();
    float sum = 0.f, sumsq = 0.f;
#pragma unroll
    for (int q = 0; q < 8; q++) { sum += red[0][q]; sumsq += red[1][q]; }
    float m   = sum * (1.0f / C2);
    float var = sumsq * (1.0f / C2) - m * m;
    float rs  = rsqrtf(var + 1e-3f);

    float4 g4 = *(const float4*)&lng[ch];
    float4 b4 = *(const float4*)&lnb[ch];
    float4 o4;
    o4.x = silu_f((v.x - m) * rs * g4.x + b4.x);
    o4.y = silu_f((v.y - m) * rs * g4.y + b4.y);
    o4.z = silu_f((v.z - m) * rs * g4.z + b4.z);
    o4.w = silu_f((v.w - m) * rs * g4.w + b4.w);

    if (src < 4) {
        size_t idx = (size_t)row * C2 + ch;   // row = src*128 + t2
        *(float4*)&g_vp[idx] = o4;
        *(float4*)&out_vp_copy[idx] = o4;
    } else {
        *(float4*)&g_sp[(size_t)(row - 4 * T2) * C2 + ch] = o4;
    }
}

// ---------------------------------------------------------------------------
// Kernel C: similarity partials per 256-d chunk.
// 256 blocks (dc, b, jt, it) x 256 threads; 32x32 tile, 2x2 per thread.
// ---------------------------------------------------------------------------
__device__ __forceinline__ float sgnx(float a, float s) {
    float b = a + s;
    unsigned int x = (__float_as_uint(a) ^ __float_as_uint(b));
    return __uint_as_float((x & 0x80000000u) | 0x3f800000u);
}

__global__ void sim_kernel() {
    __shared__ float vps[32][132];
    __shared__ float sps[32][132];

    int blk = blockIdx.x;
    int dc = blk >> 6;
    int b  = (blk >> 4) & 3;
    int jt = (blk >> 2) & 3;
    int it = blk & 3;
    int i0 = it * 32, j0 = jt * 32;
    int t  = threadIdx.x;
    int ti = (t & 15) * 2;
    int tj = (t >> 4) * 2;

    float a00 = 0.f, a01 = 0.f, a10 = 0.f, a11 = 0.f;

    for (int half = 0; half < 2; half++) {
        int d0 = dc * 256 + half * 128;
        __syncthreads();
        for (int e = t; e < 32 * 32; e += 256) {
            int r = e >> 5, c4 = e & 31;
            *(float4*)&vps[r][c4 * 4] =
                *(const float4*)&g_vp[((size_t)(b * T2 + i0 + r)) * C2 + d0 + c4 * 4];
            *(float4*)&sps[r][c4 * 4] =
                *(const float4*)&g_sp[(size_t)(j0 + r) * C2 + d0 + c4 * 4];
        }
        __syncthreads();
#pragma unroll 4
        for (int c4 = 0; c4 < 32; c4++) {
            float4 v0 = *(const float4*)&vps[ti][c4 * 4];
            float4 v1 = *(const float4*)&vps[ti + 1][c4 * 4];
            float4 s0 = *(const float4*)&sps[tj][c4 * 4];
            float4 s1 = *(const float4*)&sps[tj + 1][c4 * 4];
            a00 += sgnx(v0.x, s0.x) + sgnx(v0.y, s0.y) + sgnx(v0.z, s0.z) + sgnx(v0.w, s0.w);
            a01 += sgnx(v0.x, s1.x) + sgnx(v0.y, s1.y) + sgnx(v0.z, s1.z) + sgnx(v0.w, s1.w);
            a10 += sgnx(v1.x, s0.x) + sgnx(v1.y, s0.y) + sgnx(v1.z, s0.z) + sgnx(v1.w, s0.w);
            a11 += sgnx(v1.x, s1.x) + sgnx(v1.y, s1.y) + sgnx(v1.z, s1.z) + sgnx(v1.w, s1.w);
        }
    }

    float* Sp = g_S4 + ((size_t)dc * BATCH + b) * T2 * T2;
    size_t base = (size_t)(j0 + tj) * T2 + (i0 + ti);
    Sp[base]          = a00;
    Sp[base + 1]      = a10;
    Sp[base + T2]     = a01;
    Sp[base + T2 + 1] = a11;
}

// ---------------------------------------------------------------------------
// Kernel D: softmax (summing S4 partials) + scores @ vp + silu(attn * sp)
// 128 blocks (b, jg of 8, d-half) x 256 threads (float2 each).
// ---------------------------------------------------------------------------
__global__ void attn_kernel(float* __restrict__ out) {
    __shared__ float sc[8][T2];

    int blk = blockIdx.x;
    int b  = blk >> 5;
    int jg = (blk >> 1) & 15;
    int dh = blk & 1;
    int j0 = jg * 8;
    int d0 = dh * 512;

    int t = threadIdx.x, lane = t & 31, wrp = t >> 5;

    {   // softmax: warp w handles row j0+w
        int j = j0 + wrp;
        float v[4];
#pragma unroll
        for (int u = 0; u < 4; u++) {
            float s = 0.f;
#pragma unroll
            for (int dc = 0; dc < 4; dc++)
                s += g_S4[(((size_t)dc * BATCH + b) * T2 + j) * T2 + lane + 32 * u];
            v[u] = s * (1.0f / 1024.0f);
        }
        float mx = fmaxf(fmaxf(v[0], v[1]), fmaxf(v[2], v[3]));
#pragma unroll
        for (int off = 16; off; off >>= 1)
            mx = fmaxf(mx, __shfl_xor_sync(0xffffffffu, mx, off));
        float sum = 0.f;
#pragma unroll
        for (int u = 0; u < 4; u++) { v[u] = expf(v[u] - mx); sum += v[u]; }
#pragma unroll
        for (int off = 16; off; off >>= 1)
            sum += __shfl_xor_sync(0xffffffffu, sum, off);
        float invs = 1.0f / sum;
#pragma unroll
        for (int u = 0; u < 4; u++) sc[wrp][lane + 32 * u] = v[u] * invs;
    }
    __syncthreads();

    int d = d0 + 2 * t;
    float2 acc[8];
#pragma unroll
    for (int jl = 0; jl < 8; jl++) acc[jl] = make_float2(0.f, 0.f);

    const float* vpb = g_vp + (size_t)b * T2 * C2 + d;
#pragma unroll 4
    for (int i = 0; i < T2; i++) {
        float2 v = *(const float2*)(vpb + (size_t)i * C2);
#pragma unroll
        for (int jl = 0; jl < 8; jl++) {
            float s = sc[jl][i];
            acc[jl].x += s * v.x;
            acc[jl].y += s * v.y;
        }
    }

#pragma unroll
    for (int jl = 0; jl < 8; jl++) {
        int j = j0 + jl;
        float2 sp2 = *(const float2*)(g_sp + (size_t)j * C2 + d);
        float2 o2;
        o2.x = silu_f(acc[jl].x * sp2.x);
        o2.y = silu_f(acc[jl].y * sp2.y);
        *(float2*)(out + ((size_t)(b * T2 + j)) * C2 + d) = o2;
    }
}

// ---------------------------------------------------------------------------
extern "C" void kernel_launch(void* const* d_in, const int* in_sizes, int n_in,
                              void* d_out, int out_size) {
    const float* values  = (const float*)d_in[0];
    const float* symbols = (const float*)d_in[1];
    const float* c1w     = (const float*)d_in[2];
    const float* c1b     = (const float*)d_in[3];
    const float* l1g     = (const float*)d_in[4];
    const float* l1b     = (const float*)d_in[5];
    const float* c2w     = (const float*)d_in[6];
    const float* c2b     = (const float*)d_in[7];
    const float* l2g     = (const float*)d_in[8];
    const float* l2b     = (const float*)d_in[9];
    float* out = (float*)d_out;
    float* out_vp = out + (size_t)BATCH * T2 * C2;

    prepack<<<768, 256>>>(c1w, c2w);
    conv1_ln_silu<<<200, 256>>>(values, symbols, c1b, l1g, l1b);
    conv2_raw<<<160, 256>>>(c2b);
    ln2_silu<<<640, 256>>>(l2g, l2b, out_vp);
    sim_kernel<<<256, 256>>>();
    attn_kernel<<<128, 256>>>(out);
}

// round 5
// speedup vs baseline: 1.6454x; 1.6454x over previous
#include <cuda_runtime.h>
#include <math.h>

#define BATCH 4
#define T_IN 1920
#define E_IN 512
#define C1 128
#define T1 640
#define C2 1024
#define T2 128

// Scratch (device globals; allocations forbidden)
__device__ float  g_h1[5 * T1 * C1];             // conv1+ln1+silu output
__device__ float  g_c1p[4][5 * T1 * C1];         // conv1 partials per E-quarter
__device__ float  g_c2p[3][5 * T2 * C2];         // conv2 partials per k-tap
__device__ float  g_vp[BATCH * T2 * C2];         // values_projected
__device__ float  g_sp[T2 * C2];                 // symbol_projected
__device__ float  g_S8[8][BATCH * T2 * T2];      // similarity partials per 128-d chunk
__device__ float2 g_wpk1[5 * 256 * 128];         // conv1 w c-pair packed
__device__ float2 g_wpk2[3 * 64 * 1024];         // conv2 w c-pair packed

__device__ __forceinline__ float silu_f(float y) { return y / (1.0f + expf(-y)); }

__device__ __forceinline__ unsigned long long fma2(unsigned long long a,
                                                   unsigned long long b,
                                                   unsigned long long c) {
    unsigned long long d;
    asm("fma.rn.f32x2 %0, %1, %2, %3;" : "=l"(d) : "l"(a), "l"(b), "l"(c));
    return d;
}
__device__ __forceinline__ float pksum(unsigned long long p) {
    unsigned int lo, hi;
    asm("mov.b64 {%0, %1}, %2;" : "=r"(lo), "=r"(hi) : "l"(p));
    return __uint_as_float(lo) + __uint_as_float(hi);
}

// ---------------------------------------------------------------------------
// Kernel 0: repack conv weights into c-pair (f32x2) layout
// ---------------------------------------------------------------------------
__global__ void prepack(const float* __restrict__ w1, const float* __restrict__ w2) {
    int idx = blockIdx.x * 256 + threadIdx.x;
    if (idx < 5 * 256 * 128) {
        int o  = idx & 127;
        int c2 = (idx >> 7) & 255;
        int k  = idx >> 15;
        const float* p = w1 + ((size_t)(k * 512 + 2 * c2)) * 128 + o;
        g_wpk1[idx] = make_float2(p[0], p[128]);
    }
    if (idx < 3 * 64 * 1024) {
        int o  = idx & 1023;
        int c2 = (idx >> 10) & 63;
        int k  = idx >> 16;
        const float* p = w2 + ((size_t)(k * 128 + 2 * c2)) * 1024 + o;
        g_wpk2[idx] = make_float2(p[0], p[1024]);
    }
}

// ---------------------------------------------------------------------------
// Kernel A1: conv1 partials. grid = 5src x 20tg x 4eh = 400 blocks, 256 thr.
// Block: 32 timesteps, E-slice of 128 (staged in 2 chunks of 64).
// Warp tile: 4 timesteps x (lane: 4 channels). 32 FFMA2 per 4 LDG.128.
// ---------------------------------------------------------------------------
#define C1TS 32
#define C1ROWS (3 * (C1TS - 1) + 5)   // 98
#define EC 64

__global__ void __launch_bounds__(256) conv1_raw(const float* __restrict__ values,
                                                 const float* __restrict__ symbols) {
    __shared__ float xs[C1ROWS * EC];   // 24.5KB

    int blk = blockIdx.x;               // (src*20 + tg)*4 + eh
    int eh  = blk & 3;
    int st  = blk >> 2;                 // 0..99
    int src = st / 20;
    int tg  = st % 20;
    int t0  = tg * C1TS;
    const float* x = (src < 4) ? (values + (size_t)src * T_IN * E_IN) : symbols;
    int base_row = t0 * 3 - 1;

    int t    = threadIdx.x;
    int lane = t & 31;
    int wrp  = t >> 5;                  // 0..7
    int ch0  = lane * 4;
    int ts0  = wrp * 4;                 // 4 timesteps per warp

    unsigned long long acc[4][4];       // [ts][ch-pair]
#pragma unroll
    for (int j = 0; j < 4; j++)
#pragma unroll
        for (int q = 0; q < 4; q++) acc[j][q] = 0ULL;

#pragma unroll
    for (int ec = 0; ec < 128; ec += EC) {
        int col0 = eh * 128 + ec;
        __syncthreads();
        for (int idx = t; idx < C1ROWS * (EC / 4); idx += 256) {
            int r  = idx >> 4;          // EC/4 = 16
            int c4 = idx & 15;
            int gr = base_row + r;
            float4 v = make_float4(0.f, 0.f, 0.f, 0.f);
            if (gr >= 0 && gr < T_IN)
                v = *(const float4*)(x + (size_t)gr * E_IN + col0 + c4 * 4);
            ((float4*)xs)[idx] = v;
        }
        __syncthreads();

#pragma unroll
        for (int k = 0; k < 5; k++) {
            const float2* wrow = g_wpk1 + ((size_t)(k * 256 + (col0 >> 1))) * 128 + ch0;
            for (int c2 = 0; c2 < EC / 2; c2 += 2) {
                const float2* wq = wrow + (size_t)c2 * 128;
                ulonglong2 wA = *(const ulonglong2*)(wq);        // ch0,ch0+1 @ c2
                ulonglong2 wB = *(const ulonglong2*)(wq + 2);    // ch0+2,3  @ c2
                ulonglong2 wC = *(const ulonglong2*)(wq + 128);  // ch0,ch0+1 @ c2+1
                ulonglong2 wD = *(const ulonglong2*)(wq + 130);  // ch0+2,3  @ c2+1
#pragma unroll
                for (int j = 0; j < 4; j++) {
                    // pair c2 covers channels 2*c2..2*c2+3 -> column 2*c2
                    ulonglong2 xv = *(const ulonglong2*)&xs[(3 * (ts0 + j) + k) * EC + 2 * c2];
                    acc[j][0] = fma2(xv.x, wA.x, acc[j][0]);
                    acc[j][1] = fma2(xv.x, wA.y, acc[j][1]);
                    acc[j][2] = fma2(xv.x, wB.x, acc[j][2]);
                    acc[j][3] = fma2(xv.x, wB.y, acc[j][3]);
                    acc[j][0] = fma2(xv.y, wC.x, acc[j][0]);
                    acc[j][1] = fma2(xv.y, wC.y, acc[j][1]);
                    acc[j][2] = fma2(xv.y, wD.x, acc[j][2]);
                    acc[j][3] = fma2(xv.y, wD.y, acc[j][3]);
                }
            }
        }
    }

    float* outp = g_c1p[eh];
#pragma unroll
    for (int j = 0; j < 4; j++) {
        float4 o4;
        o4.x = pksum(acc[j][0]);
        o4.y = pksum(acc[j][1]);
        o4.z = pksum(acc[j][2]);
        o4.w = pksum(acc[j][3]);
        *(float4*)&outp[((size_t)src * T1 + (t0 + ts0 + j)) * C1 + ch0] = o4;
    }
}

// ---------------------------------------------------------------------------
// Kernel A2: sum conv1 partials + bias + layernorm(128) + silu -> g_h1
// 400 blocks x 256 thr; warp = 1 row, lane = 4 channels (warp-local LN).
// ---------------------------------------------------------------------------
__global__ void ln1_silu(const float* __restrict__ bias,
                         const float* __restrict__ lng,
                         const float* __restrict__ lnb) {
    int row  = blockIdx.x * 8 + (threadIdx.x >> 5);   // 0..3199
    int lane = threadIdx.x & 31;
    int ch0  = lane * 4;
    size_t off = (size_t)row * C1 + ch0;

    float4 v = *(const float4*)&bias[ch0];
#pragma unroll
    for (int eh = 0; eh < 4; eh++) {
        float4 p = *(const float4*)&g_c1p[eh][off];
        v.x += p.x; v.y += p.y; v.z += p.z; v.w += p.w;
    }
    float s  = v.x + v.y + v.z + v.w;
    float s2 = v.x * v.x + v.y * v.y + v.z * v.z + v.w * v.w;
#pragma unroll
    for (int o = 16; o; o >>= 1) {
        s  += __shfl_xor_sync(0xffffffffu, s,  o);
        s2 += __shfl_xor_sync(0xffffffffu, s2, o);
    }
    float m   = s * (1.0f / C1);
    float var = s2 * (1.0f / C1) - m * m;
    float rs  = rsqrtf(var + 1e-3f);
    float4 g4 = *(const float4*)&lng[ch0];
    float4 b4 = *(const float4*)&lnb[ch0];
    float4 o4;
    o4.x = silu_f((v.x - m) * rs * g4.x + b4.x);
    o4.y = silu_f((v.y - m) * rs * g4.y + b4.y);
    o4.z = silu_f((v.z - m) * rs * g4.z + b4.z);
    o4.w = silu_f((v.w - m) * rs * g4.w + b4.w);
    *(float4*)&g_h1[off] = o4;
}

// ---------------------------------------------------------------------------
// Kernel B1: conv2 partials per k-tap. grid = 5src x 16tg x 2chh x 3k = 480.
// 256 thr; thread = 2 channels x 8 timesteps. Single k => 8 staged rows.
// ---------------------------------------------------------------------------
__global__ void __launch_bounds__(256) conv2_raw() {
    __shared__ float xs[8 * C1];   // 4KB

    int blk = blockIdx.x;
    int k   = blk % 3;
    int r1  = blk / 3;              // (src*16 + tg)*2 + chh
    int chh = r1 & 1;
    int st  = r1 >> 1;
    int src = st >> 4;
    int tg  = st & 15;
    int t0  = tg * 8;

    int t   = threadIdx.x;
    int ch0 = chh * 512 + t * 2;

    // stage rows 5*(t0+j)+k, j=0..7
    {
        int j  = t >> 5;
        int c4 = t & 31;
        const float* src_row = g_h1 + ((size_t)src * T1 + 5 * (t0 + j) + k) * C1;
        ((float4*)xs)[t] = *(const float4*)(src_row + c4 * 4);
    }
    __syncthreads();

    unsigned long long acc[8][2];
#pragma unroll
    for (int j = 0; j < 8; j++) { acc[j][0] = 0ULL; acc[j][1] = 0ULL; }

    const float2* wrow = g_wpk2 + (size_t)(k * 64) * 1024 + ch0;
    for (int c2 = 0; c2 < 64; c2 += 2) {
        ulonglong2 w0 = *(const ulonglong2*)(wrow + (size_t)c2 * 1024);        // c2
        ulonglong2 w1 = *(const ulonglong2*)(wrow + (size_t)(c2 + 1) * 1024);  // c2+1
#pragma unroll
        for (int j = 0; j < 8; j++) {
            ulonglong2 xv = *(const ulonglong2*)&xs[j * C1 + 2 * c2];
            acc[j][0] = fma2(xv.x, w0.x, acc[j][0]);
            acc[j][1] = fma2(xv.x, w0.y, acc[j][1]);
            acc[j][0] = fma2(xv.y, w1.x, acc[j][0]);
            acc[j][1] = fma2(xv.y, w1.y, acc[j][1]);
        }
    }

    float* outp = g_c2p[k];
#pragma unroll
    for (int j = 0; j < 8; j++) {
        float2 o2 = make_float2(pksum(acc[j][0]), pksum(acc[j][1]));
        *(float2*)&outp[((size_t)(src * T2 + t0 + j)) * C2 + ch0] = o2;
    }
}

// ---------------------------------------------------------------------------
// Kernel B2: sum conv2 partials + bias + layernorm(1024) + silu
// 640 blocks x 256 thr.
// ---------------------------------------------------------------------------
__global__ void ln2_silu(const float* __restrict__ bias,
                         const float* __restrict__ lng,
                         const float* __restrict__ lnb,
                         float* __restrict__ out_vp_copy) {
    __shared__ float red[2][8];
    int row = blockIdx.x;
    int src = row >> 7;
    int t = threadIdx.x, lane = t & 31, wid = t >> 5;
    int ch = 4 * t;
    size_t off = (size_t)row * C2 + ch;

    float4 v = *(const float4*)&bias[ch];
#pragma unroll
    for (int k = 0; k < 3; k++) {
        float4 p = *(const float4*)&g_c2p[k][off];
        v.x += p.x; v.y += p.y; v.z += p.z; v.w += p.w;
    }
    float s  = v.x + v.y + v.z + v.w;
    float s2 = v.x * v.x + v.y * v.y + v.z * v.z + v.w * v.w;
#pragma unroll
    for (int o = 16; o; o >>= 1) {
        s  += __shfl_xor_sync(0xffffffffu, s,  o);
        s2 += __shfl_xor_sync(0xffffffffu, s2, o);
    }
    if (lane == 0) { red[0][wid] = s; red[1][wid] = s2; }
    __syncthreads();
    float sum = 0.f, sumsq = 0.f;
#pragma unroll
    for (int q = 0; q < 8; q++) { sum += red[0][q]; sumsq += red[1][q]; }
    float m   = sum * (1.0f / C2);
    float var = sumsq * (1.0f / C2) - m * m;
    float rs  = rsqrtf(var + 1e-3f);

    float4 g4 = *(const float4*)&lng[ch];
    float4 b4 = *(const float4*)&lnb[ch];
    float4 o4;
    o4.x = silu_f((v.x - m) * rs * g4.x + b4.x);
    o4.y = silu_f((v.y - m) * rs * g4.y + b4.y);
    o4.z = silu_f((v.z - m) * rs * g4.z + b4.z);
    o4.w = silu_f((v.w - m) * rs * g4.w + b4.w);

    if (src < 4) {
        *(float4*)&g_vp[off] = o4;
        *(float4*)&out_vp_copy[off] = o4;
    } else {
        *(float4*)&g_sp[(size_t)(row - 4 * T2) * C2 + ch] = o4;
    }
}

// ---------------------------------------------------------------------------
// Kernel C: similarity partials per 128-d chunk.
// 512 blocks (dc8, b4, jt4, it4) x 256 thr; 32x32 tile, 2x2 per thread.
// ---------------------------------------------------------------------------
__device__ __forceinline__ float sgnx(float a, float s) {
    float b = a + s;
    unsigned int x = (__float_as_uint(a) ^ __float_as_uint(b));
    return __uint_as_float((x & 0x80000000u) | 0x3f800000u);
}

__global__ void sim_kernel() {
    __shared__ float vps[32][132];
    __shared__ float sps[32][132];

    int blk = blockIdx.x;
    int dc = blk >> 6;
    int b  = (blk >> 4) & 3;
    int jt = (blk >> 2) & 3;
    int it = blk & 3;
    int i0 = it * 32, j0 = jt * 32;
    int d0 = dc * 128;
    int t  = threadIdx.x;
    int ti = (t & 15) * 2;
    int tj = (t >> 4) * 2;

    for (int e = t; e < 32 * 32; e += 256) {
        int r = e >> 5, c4 = e & 31;
        *(float4*)&vps[r][c4 * 4] =
            *(const float4*)&g_vp[((size_t)(b * T2 + i0 + r)) * C2 + d0 + c4 * 4];
        *(float4*)&sps[r][c4 * 4] =
            *(const float4*)&g_sp[(size_t)(j0 + r) * C2 + d0 + c4 * 4];
    }
    __syncthreads();

    float a00 = 0.f, a01 = 0.f, a10 = 0.f, a11 = 0.f;
#pragma unroll 4
    for (int c4 = 0; c4 < 32; c4++) {
        float4 v0 = *(const float4*)&vps[ti][c4 * 4];
        float4 v1 = *(const float4*)&vps[ti + 1][c4 * 4];
        float4 s0 = *(const float4*)&sps[tj][c4 * 4];
        float4 s1 = *(const float4*)&sps[tj + 1][c4 * 4];
        a00 += sgnx(v0.x, s0.x) + sgnx(v0.y, s0.y) + sgnx(v0.z, s0.z) + sgnx(v0.w, s0.w);
        a01 += sgnx(v0.x, s1.x) + sgnx(v0.y, s1.y) + sgnx(v0.z, s1.z) + sgnx(v0.w, s1.w);
        a10 += sgnx(v1.x, s0.x) + sgnx(v1.y, s0.y) + sgnx(v1.z, s0.z) + sgnx(v1.w, s0.w);
        a11 += sgnx(v1.x, s1.x) + sgnx(v1.y, s1.y) + sgnx(v1.z, s1.z) + sgnx(v1.w, s1.w);
    }

    float* Sp = g_S8[dc] + (size_t)b * T2 * T2;
    size_t base = (size_t)(j0 + tj) * T2 + (i0 + ti);
    Sp[base]          = a00;
    Sp[base + 1]      = a10;
    Sp[base + T2]     = a01;
    Sp[base + T2 + 1] = a11;
}

// ---------------------------------------------------------------------------
// Kernel D: softmax (summing S8 partials) + scores @ vp + silu(attn * sp)
// 256 blocks (b4, jg16 of 8 rows, dq4 of 256 d) x 128 thr (float2 each).
// ---------------------------------------------------------------------------
__global__ void attn_kernel(float* __restrict__ out) {
    __shared__ float sc[8][T2];

    int blk = blockIdx.x;
    int b  = blk >> 6;
    int jg = (blk >> 2) & 15;
    int dq = blk & 3;
    int j0 = jg * 8;
    int d0 = dq * 256;

    int t = threadIdx.x, lane = t & 31, wrp = t >> 5;

#pragma unroll
    for (int rr = 0; rr < 2; rr++) {       // 4 warps x 2 rows
        int j = j0 + wrp * 2 + rr;
        float v[4];
#pragma unroll
        for (int u = 0; u < 4; u++) {
            float s = 0.f;
#pragma unroll
            for (int dc = 0; dc < 8; dc++)
                s += g_S8[dc][((size_t)b * T2 + j) * T2 + lane + 32 * u];
            v[u] = s * (1.0f / 1024.0f);
        }
        float mx = fmaxf(fmaxf(v[0], v[1]), fmaxf(v[2], v[3]));
#pragma unroll
        for (int o = 16; o; o >>= 1)
            mx = fmaxf(mx, __shfl_xor_sync(0xffffffffu, mx, o));
        float sum = 0.f;
#pragma unroll
        for (int u = 0; u < 4; u++) { v[u] = expf(v[u] - mx); sum += v[u]; }
#pragma unroll
        for (int o = 16; o; o >>= 1)
            sum += __shfl_xor_sync(0xffffffffu, sum, o);
        float invs = 1.0f / sum;
#pragma unroll
        for (int u = 0; u < 4; u++) sc[wrp * 2 + rr][lane + 32 * u] = v[u] * invs;
    }
    __syncthreads();

    int d = d0 + 2 * t;
    float2 acc[8];
#pragma unroll
    for (int jl = 0; jl < 8; jl++) acc[jl] = make_float2(0.f, 0.f);

    const float* vpb = g_vp + (size_t)b * T2 * C2 + d;
#pragma unroll 8
    for (int i = 0; i < T2; i++) {
        float2 v = *(const float2*)(vpb + (size_t)i * C2);
#pragma unroll
        for (int jl = 0; jl < 8; jl++) {
            float s = sc[jl][i];
            acc[jl].x += s * v.x;
            acc[jl].y += s * v.y;
        }
    }

#pragma unroll
    for (int jl = 0; jl < 8; jl++) {
        int j = j0 + jl;
        float2 sp2 = *(const float2*)(g_sp + (size_t)j * C2 + d);
        float2 o2;
        o2.x = silu_f(acc[jl].x * sp2.x);
        o2.y = silu_f(acc[jl].y * sp2.y);
        *(float2*)(out + ((size_t)(b * T2 + j)) * C2 + d) = o2;
    }
}

// ---------------------------------------------------------------------------
extern "C" void kernel_launch(void* const* d_in, const int* in_sizes, int n_in,
                              void* d_out, int out_size) {
    const float* values  = (const float*)d_in[0];
    const float* symbols = (const float*)d_in[1];
    const float* c1w     = (const float*)d_in[2];
    const float* c1b     = (const float*)d_in[3];
    const float* l1g     = (const float*)d_in[4];
    const float* l1b     = (const float*)d_in[5];
    const float* c2w     = (const float*)d_in[6];
    const float* c2b     = (const float*)d_in[7];
    const float* l2g     = (const float*)d_in[8];
    const float* l2b     = (const float*)d_in[9];
    float* out = (float*)d_out;
    float* out_vp = out + (size_t)BATCH * T2 * C2;

    prepack<<<768, 256>>>(c1w, c2w);
    conv1_raw<<<400, 256>>>(values, symbols);
    ln1_silu<<<400, 256>>>(c1b, l1g, l1b);
    conv2_raw<<<480, 256>>>();
    ln2_silu<<<640, 256>>>(c2b, l2g, l2b, out_vp);
    sim_kernel<<<512, 256>>>();
    attn_kernel<<<256, 128>>>(out);
}

// round 6
// speedup vs baseline: 1.8207x; 1.1066x over previous
#include <cuda_runtime.h>
#include <math.h>

#define BATCH 4
#define T_IN 1920
#define E_IN 512
#define C1 128
#define T1 640
#define C2 1024
#define T2 128

// Scratch (device globals; allocations forbidden)
__device__ float  g_h1[5 * T1 * C1];             // conv1+ln1+silu output
__device__ float  g_c1p[8][5 * T1 * C1];         // conv1 partials per E-eighth
__device__ float  g_c2p[3][5 * T2 * C2];         // conv2 partials per k-tap
__device__ float  g_vp[BATCH * T2 * C2];         // values_projected
__device__ float  g_sp[T2 * C2];                 // symbol_projected
__device__ float  g_S8[8][BATCH * T2 * T2];      // similarity partials per 128-d chunk
__device__ float2 g_wpk1[5 * 256 * 128];         // conv1 w c-pair packed
__device__ float2 g_wpk2[3 * 64 * 1024];         // conv2 w c-pair packed

__device__ __forceinline__ float silu_f(float y) { return y / (1.0f + expf(-y)); }

__device__ __forceinline__ unsigned long long fma2(unsigned long long a,
                                                   unsigned long long b,
                                                   unsigned long long c) {
    unsigned long long d;
    asm("fma.rn.f32x2 %0, %1, %2, %3;" : "=l"(d) : "l"(a), "l"(b), "l"(c));
    return d;
}
__device__ __forceinline__ float pksum(unsigned long long p) {
    unsigned int lo, hi;
    asm("mov.b64 {%0, %1}, %2;" : "=r"(lo), "=r"(hi) : "l"(p));
    return __uint_as_float(lo) + __uint_as_float(hi);
}

// ---------------------------------------------------------------------------
// Kernel 0: repack conv weights into c-pair (f32x2) layout
// ---------------------------------------------------------------------------
__global__ void prepack(const float* __restrict__ w1, const float* __restrict__ w2) {
    int idx = blockIdx.x * 256 + threadIdx.x;
    if (idx < 5 * 256 * 128) {
        int o  = idx & 127;
        int c2 = (idx >> 7) & 255;
        int k  = idx >> 15;
        const float* p = w1 + ((size_t)(k * 512 + 2 * c2)) * 128 + o;
        g_wpk1[idx] = make_float2(p[0], p[128]);
    }
    if (idx < 3 * 64 * 1024) {
        int o  = idx & 1023;
        int c2 = (idx >> 10) & 63;
        int k  = idx >> 16;
        const float* p = w2 + ((size_t)(k * 128 + 2 * c2)) * 1024 + o;
        g_wpk2[idx] = make_float2(p[0], p[1024]);
    }
}

// ---------------------------------------------------------------------------
// Kernel A1: conv1 partials. grid = 5src x 20tg x 8eh = 800 blocks, 256 thr.
// Block: 32 timesteps, E-slice of 64 (single smem stage, 25KB).
// Warp tile: 4 timesteps x (lane: 4 channels).
// ---------------------------------------------------------------------------
#define C1TS 32
#define C1ROWS (3 * (C1TS - 1) + 5)   // 98
#define EC 64

__global__ void __launch_bounds__(256) conv1_raw(const float* __restrict__ values,
                                                 const float* __restrict__ symbols) {
    __shared__ float xs[C1ROWS * EC];   // 25KB

    int blk = blockIdx.x;               // (src*20 + tg)*8 + eh
    int eh  = blk & 7;
    int st  = blk >> 3;                 // 0..99
    int src = st / 20;
    int tg  = st % 20;
    int t0  = tg * C1TS;
    const float* x = (src < 4) ? (values + (size_t)src * T_IN * E_IN) : symbols;
    int base_row = t0 * 3 - 1;
    int col0 = eh * EC;

    int t    = threadIdx.x;
    int lane = t & 31;
    int wrp  = t >> 5;                  // 0..7
    int ch0  = lane * 4;
    int ts0  = wrp * 4;                 // 4 timesteps per warp

    // stage 98 rows x 64 cols
    for (int idx = t; idx < C1ROWS * (EC / 4); idx += 256) {
        int r  = idx >> 4;              // EC/4 = 16
        int c4 = idx & 15;
        int gr = base_row + r;
        float4 v = make_float4(0.f, 0.f, 0.f, 0.f);
        if (gr >= 0 && gr < T_IN)
            v = *(const float4*)(x + (size_t)gr * E_IN + col0 + c4 * 4);
        ((float4*)xs)[idx] = v;
    }
    __syncthreads();

    unsigned long long acc[4][4];       // [ts][ch-pair]
#pragma unroll
    for (int j = 0; j < 4; j++)
#pragma unroll
        for (int q = 0; q < 4; q++) acc[j][q] = 0ULL;

#pragma unroll
    for (int k = 0; k < 5; k++) {
        const float2* wrow = g_wpk1 + ((size_t)(k * 256 + eh * 32)) * 128 + ch0;
#pragma unroll 4
        for (int c2 = 0; c2 < EC / 2; c2 += 2) {   // pairs c2, c2+1
            const float2* wq = wrow + (size_t)c2 * 128;
            ulonglong2 wA = *(const ulonglong2*)(wq);        // ch0,ch0+1 @ c2
            ulonglong2 wB = *(const ulonglong2*)(wq + 2);    // ch0+2,3  @ c2
            ulonglong2 wC = *(const ulonglong2*)(wq + 128);  // ch0,ch0+1 @ c2+1
            ulonglong2 wD = *(const ulonglong2*)(wq + 130);  // ch0+2,3  @ c2+1
#pragma unroll
            for (int j = 0; j < 4; j++) {
                ulonglong2 xv = *(const ulonglong2*)&xs[(3 * (ts0 + j) + k) * EC + 2 * c2];
                acc[j][0] = fma2(xv.x, wA.x, acc[j][0]);
                acc[j][1] = fma2(xv.x, wA.y, acc[j][1]);
                acc[j][2] = fma2(xv.x, wB.x, acc[j][2]);
                acc[j][3] = fma2(xv.x, wB.y, acc[j][3]);
                acc[j][0] = fma2(xv.y, wC.x, acc[j][0]);
                acc[j][1] = fma2(xv.y, wC.y, acc[j][1]);
                acc[j][2] = fma2(xv.y, wD.x, acc[j][2]);
                acc[j][3] = fma2(xv.y, wD.y, acc[j][3]);
            }
        }
    }

    float* outp = g_c1p[eh];
#pragma unroll
    for (int j = 0; j < 4; j++) {
        float4 o4;
        o4.x = pksum(acc[j][0]);
        o4.y = pksum(acc[j][1]);
        o4.z = pksum(acc[j][2]);
        o4.w = pksum(acc[j][3]);
        *(float4*)&outp[((size_t)src * T1 + (t0 + ts0 + j)) * C1 + ch0] = o4;
    }
}

// ---------------------------------------------------------------------------
// Kernel A2: sum conv1 partials + bias + layernorm(128) + silu -> g_h1
// 400 blocks x 256 thr; warp = 1 row, lane = 4 channels (warp-local LN).
// ---------------------------------------------------------------------------
__global__ void ln1_silu(const float* __restrict__ bias,
                         const float* __restrict__ lng,
                         const float* __restrict__ lnb) {
    int row  = blockIdx.x * 8 + (threadIdx.x >> 5);   // 0..3199
    int lane = threadIdx.x & 31;
    int ch0  = lane * 4;
    size_t off = (size_t)row * C1 + ch0;

    float4 v = *(const float4*)&bias[ch0];
#pragma unroll
    for (int eh = 0; eh < 8; eh++) {
        float4 p = *(const float4*)&g_c1p[eh][off];
        v.x += p.x; v.y += p.y; v.z += p.z; v.w += p.w;
    }
    float s  = v.x + v.y + v.z + v.w;
    float s2 = v.x * v.x + v.y * v.y + v.z * v.z + v.w * v.w;
#pragma unroll
    for (int o = 16; o; o >>= 1) {
        s  += __shfl_xor_sync(0xffffffffu, s,  o);
        s2 += __shfl_xor_sync(0xffffffffu, s2, o);
    }
    float m   = s * (1.0f / C1);
    float var = s2 * (1.0f / C1) - m * m;
    float rs  = rsqrtf(var + 1e-3f);
    float4 g4 = *(const float4*)&lng[ch0];
    float4 b4 = *(const float4*)&lnb[ch0];
    float4 o4;
    o4.x = silu_f((v.x - m) * rs * g4.x + b4.x);
    o4.y = silu_f((v.y - m) * rs * g4.y + b4.y);
    o4.z = silu_f((v.z - m) * rs * g4.z + b4.z);
    o4.w = silu_f((v.w - m) * rs * g4.w + b4.w);
    *(float4*)&g_h1[off] = o4;
}

// ---------------------------------------------------------------------------
// Kernel B1: conv2 partials per k-tap. grid = 5src x 16tg x 2chh x 3k = 480.
// 256 thr; thread = 2 channels x 8 timesteps. Single k => 8 staged rows.
// ---------------------------------------------------------------------------
__global__ void __launch_bounds__(256) conv2_raw() {
    __shared__ float xs[8 * C1];   // 4KB

    int blk = blockIdx.x;
    int k   = blk % 3;
    int r1  = blk / 3;              // (src*16 + tg)*2 + chh
    int chh = r1 & 1;
    int st  = r1 >> 1;
    int src = st >> 4;
    int tg  = st & 15;
    int t0  = tg * 8;

    int t   = threadIdx.x;
    int ch0 = chh * 512 + t * 2;

    // stage rows 5*(t0+j)+k, j=0..7
    {
        int j  = t >> 5;
        int c4 = t & 31;
        const float* src_row = g_h1 + ((size_t)src * T1 + 5 * (t0 + j) + k) * C1;
        ((float4*)xs)[t] = *(const float4*)(src_row + c4 * 4);
    }
    __syncthreads();

    unsigned long long acc[8][2];
#pragma unroll
    for (int j = 0; j < 8; j++) { acc[j][0] = 0ULL; acc[j][1] = 0ULL; }

    const float2* wrow = g_wpk2 + (size_t)(k * 64) * 1024 + ch0;
#pragma unroll 4
    for (int c2 = 0; c2 < 64; c2 += 2) {
        ulonglong2 w0 = *(const ulonglong2*)(wrow + (size_t)c2 * 1024);        // c2
        ulonglong2 w1 = *(const ulonglong2*)(wrow + (size_t)(c2 + 1) * 1024);  // c2+1
#pragma unroll
        for (int j = 0; j < 8; j++) {
            ulonglong2 xv = *(const ulonglong2*)&xs[j * C1 + 2 * c2];
            acc[j][0] = fma2(xv.x, w0.x, acc[j][0]);
            acc[j][1] = fma2(xv.x, w0.y, acc[j][1]);
            acc[j][0] = fma2(xv.y, w1.x, acc[j][0]);
            acc[j][1] = fma2(xv.y, w1.y, acc[j][1]);
        }
    }

    float* outp = g_c2p[k];
#pragma unroll
    for (int j = 0; j < 8; j++) {
        float2 o2 = make_float2(pksum(acc[j][0]), pksum(acc[j][1]));
        *(float2*)&outp[((size_t)(src * T2 + t0 + j)) * C2 + ch0] = o2;
    }
}

// ---------------------------------------------------------------------------
// Kernel B2: sum conv2 partials + bias + layernorm(1024) + silu
// 640 blocks x 256 thr.
// ---------------------------------------------------------------------------
__global__ void ln2_silu(const float* __restrict__ bias,
                         const float* __restrict__ lng,
                         const float* __restrict__ lnb,
                         float* __restrict__ out_vp_copy) {
    __shared__ float red[2][8];
    int row = blockIdx.x;
    int src = row >> 7;
    int t = threadIdx.x, lane = t & 31, wid = t >> 5;
    int ch = 4 * t;
    size_t off = (size_t)row * C2 + ch;

    float4 v = *(const float4*)&bias[ch];
#pragma unroll
    for (int k = 0; k < 3; k++) {
        float4 p = *(const float4*)&g_c2p[k][off];
        v.x += p.x; v.y += p.y; v.z += p.z; v.w += p.w;
    }
    float s  = v.x + v.y + v.z + v.w;
    float s2 = v.x * v.x + v.y * v.y + v.z * v.z + v.w * v.w;
#pragma unroll
    for (int o = 16; o; o >>= 1) {
        s  += __shfl_xor_sync(0xffffffffu, s,  o);
        s2 += __shfl_xor_sync(0xffffffffu, s2, o);
    }
    if (lane == 0) { red[0][wid] = s; red[1][wid] = s2; }
    __syncthreads();
    float sum = 0.f, sumsq = 0.f;
#pragma unroll
    for (int q = 0; q < 8; q++) { sum += red[0][q]; sumsq += red[1][q]; }
    float m   = sum * (1.0f / C2);
    float var = sumsq * (1.0f / C2) - m * m;
    float rs  = rsqrtf(var + 1e-3f);

    float4 g4 = *(const float4*)&lng[ch];
    float4 b4 = *(const float4*)&lnb[ch];
    float4 o4;
    o4.x = silu_f((v.x - m) * rs * g4.x + b4.x);
    o4.y = silu_f((v.y - m) * rs * g4.y + b4.y);
    o4.z = silu_f((v.z - m) * rs * g4.z + b4.z);
    o4.w = silu_f((v.w - m) * rs * g4.w + b4.w);

    if (src < 4) {
        *(float4*)&g_vp[off] = o4;
        *(float4*)&out_vp_copy[off] = o4;
    } else {
        *(float4*)&g_sp[(size_t)(row - 4 * T2) * C2 + ch] = o4;
    }
}

// ---------------------------------------------------------------------------
// Kernel C: similarity partials per 128-d chunk.
// 512 blocks (dc8, b4, jt4, it4) x 256 thr; 32x32 tile, 2x2 per thread
// with ti/ti+16 mapping (2-way instead of 4-way smem conflicts).
// ---------------------------------------------------------------------------
__device__ __forceinline__ float sgnx(float a, float s) {
    float b = a + s;
    unsigned int x = (__float_as_uint(a) ^ __float_as_uint(b));
    return __uint_as_float((x & 0x80000000u) | 0x3f800000u);
}

__global__ void sim_kernel() {
    __shared__ float vps[32][132];
    __shared__ float sps[32][132];

    int blk = blockIdx.x;
    int dc = blk >> 6;
    int b  = (blk >> 4) & 3;
    int jt = (blk >> 2) & 3;
    int it = blk & 3;
    int i0 = it * 32, j0 = jt * 32;
    int d0 = dc * 128;
    int t  = threadIdx.x;
    int ti = t & 15;
    int tj = t >> 4;

    for (int e = t; e < 32 * 32; e += 256) {
        int r = e >> 5, c4 = e & 31;
        *(float4*)&vps[r][c4 * 4] =
            *(const float4*)&g_vp[((size_t)(b * T2 + i0 + r)) * C2 + d0 + c4 * 4];
        *(float4*)&sps[r][c4 * 4] =
            *(const float4*)&g_sp[(size_t)(j0 + r) * C2 + d0 + c4 * 4];
    }
    __syncthreads();

    float a00 = 0.f, a01 = 0.f, a10 = 0.f, a11 = 0.f;
#pragma unroll 4
    for (int c4 = 0; c4 < 32; c4++) {
        float4 v0 = *(const float4*)&vps[ti][c4 * 4];
        float4 v1 = *(const float4*)&vps[ti + 16][c4 * 4];
        float4 s0 = *(const float4*)&sps[tj][c4 * 4];
        float4 s1 = *(const float4*)&sps[tj + 16][c4 * 4];
        a00 += sgnx(v0.x, s0.x) + sgnx(v0.y, s0.y) + sgnx(v0.z, s0.z) + sgnx(v0.w, s0.w);
        a01 += sgnx(v0.x, s1.x) + sgnx(v0.y, s1.y) + sgnx(v0.z, s1.z) + sgnx(v0.w, s1.w);
        a10 += sgnx(v1.x, s0.x) + sgnx(v1.y, s0.y) + sgnx(v1.z, s0.z) + sgnx(v1.w, s0.w);
        a11 += sgnx(v1.x, s1.x) + sgnx(v1.y, s1.y) + sgnx(v1.z, s1.z) + sgnx(v1.w, s1.w);
    }

    float* Sp = g_S8[dc] + (size_t)b * T2 * T2;
    Sp[(size_t)(j0 + tj) * T2 + (i0 + ti)]            = a00;
    Sp[(size_t)(j0 + tj) * T2 + (i0 + ti + 16)]       = a10;
    Sp[(size_t)(j0 + tj + 16) * T2 + (i0 + ti)]       = a01;
    Sp[(size_t)(j0 + tj + 16) * T2 + (i0 + ti + 16)]  = a11;
}

// ---------------------------------------------------------------------------
// Kernel D: softmax (summing S8 partials) + scores @ vp + silu(attn * sp)
// 512 blocks (b4, jg16 of 8 rows, dq8 of 128 d) x 128 thr (1 float each).
// ---------------------------------------------------------------------------
__global__ void attn_kernel(float* __restrict__ out) {
    __shared__ float sc[8][T2];

    int blk = blockIdx.x;
    int b  = blk >> 7;
    int jg = (blk >> 3) & 15;
    int dq = blk & 7;
    int j0 = jg * 8;
    int d0 = dq * 128;

    int t = threadIdx.x, lane = t & 31, wrp = t >> 5;

#pragma unroll
    for (int rr = 0; rr < 2; rr++) {       // 4 warps x 2 rows
        int j = j0 + wrp * 2 + rr;
        float v[4];
#pragma unroll
        for (int u = 0; u < 4; u++) {
            float s = 0.f;
#pragma unroll
            for (int dc = 0; dc < 8; dc++)
                s += g_S8[dc][((size_t)b * T2 + j) * T2 + lane + 32 * u];
            v[u] = s * (1.0f / 1024.0f);
        }
        float mx = fmaxf(fmaxf(v[0], v[1]), fmaxf(v[2], v[3]));
#pragma unroll
        for (int o = 16; o; o >>= 1)
            mx = fmaxf(mx, __shfl_xor_sync(0xffffffffu, mx, o));
        float sum = 0.f;
#pragma unroll
        for (int u = 0; u < 4; u++) { v[u] = expf(v[u] - mx); sum += v[u]; }
#pragma unroll
        for (int o = 16; o; o >>= 1)
            sum += __shfl_xor_sync(0xffffffffu, sum, o);
        float invs = 1.0f / sum;
#pragma unroll
        for (int u = 0; u < 4; u++) sc[wrp * 2 + rr][lane + 32 * u] = v[u] * invs;
    }
    __syncthreads();

    int d = d0 + t;
    float acc[8];
#pragma unroll
    for (int jl = 0; jl < 8; jl++) acc[jl] = 0.f;

    const float* vpb = g_vp + (size_t)b * T2 * C2 + d;
#pragma unroll 8
    for (int i = 0; i < T2; i++) {
        float v = vpb[(size_t)i * C2];
#pragma unroll
        for (int jl = 0; jl < 8; jl++)
            acc[jl] += sc[jl][i] * v;
    }

#pragma unroll
    for (int jl = 0; jl < 8; jl++) {
        int j = j0 + jl;
        float spv = g_sp[(size_t)j * C2 + d];
        out[((size_t)(b * T2 + j)) * C2 + d] = silu_f(acc[jl] * spv);
    }
}

// ---------------------------------------------------------------------------
extern "C" void kernel_launch(void* const* d_in, const int* in_sizes, int n_in,
                              void* d_out, int out_size) {
    const float* values  = (const float*)d_in[0];
    const float* symbols = (const float*)d_in[1];
    const float* c1w     = (const float*)d_in[2];
    const float* c1b     = (const float*)d_in[3];
    const float* l1g     = (const float*)d_in[4];
    const float* l1b     = (const float*)d_in[5];
    const float* c2w     = (const float*)d_in[6];
    const float* c2b     = (const float*)d_in[7];
    const float* l2g     = (const float*)d_in[8];
    const float* l2b     = (const float*)d_in[9];
    float* out = (float*)d_out;
    float* out_vp = out + (size_t)BATCH * T2 * C2;

    prepack<<<768, 256>>>(c1w, c2w);
    conv1_raw<<<800, 256>>>(values, symbols);
    ln1_silu<<<400, 256>>>(c1b, l1g, l1b);
    conv2_raw<<<480, 256>>>();
    ln2_silu<<<640, 256>>>(c2b, l2g, l2b, out_vp);
    sim_kernel<<<512, 256>>>();
    attn_kernel<<<512, 128>>>(out);
}

// round 7
// speedup vs baseline: 2.1671x; 1.1902x over previous
#include <cuda_runtime.h>
#include <math.h>

#define BATCH 4
#define T_IN 1920
#define E_IN 512
#define C1 128
#define T1 640
#define C2 1024
#define T2 128

// Scratch (device globals; allocations forbidden)
__device__ float  g_h1[5 * T1 * C1];             // conv1+ln1+silu output
__device__ float  g_c1p[8][5 * T1 * C1];         // conv1 partials per E-eighth
__device__ float  g_c2p[3][5 * T2 * C2];         // conv2 partials per k-tap
__device__ float  g_vp[BATCH * T2 * C2];         // values_projected
__device__ float  g_sp[T2 * C2];                 // symbol_projected
__device__ float  g_S8[8][BATCH * T2 * T2];      // similarity partials per 128-d chunk
__device__ float2 g_wpk1[5 * 256 * 128];         // conv1 w c-pair packed
__device__ float2 g_wpk2[3 * 64 * 1024];         // conv2 w c-pair packed

__device__ __forceinline__ float silu_f(float y) { return y / (1.0f + expf(-y)); }

__device__ __forceinline__ unsigned long long fma2(unsigned long long a,
                                                   unsigned long long b,
                                                   unsigned long long c) {
    unsigned long long d;
    asm("fma.rn.f32x2 %0, %1, %2, %3;" : "=l"(d) : "l"(a), "l"(b), "l"(c));
    return d;
}
__device__ __forceinline__ float pksum(unsigned long long p) {
    unsigned int lo, hi;
    asm("mov.b64 {%0, %1}, %2;" : "=r"(lo), "=r"(hi) : "l"(p));
    return __uint_as_float(lo) + __uint_as_float(hi);
}

// ---------------------------------------------------------------------------
// Kernel 0: repack conv weights into c-pair (f32x2) layout
// ---------------------------------------------------------------------------
__global__ void prepack(const float* __restrict__ w1, const float* __restrict__ w2) {
    int idx = blockIdx.x * 256 + threadIdx.x;
    if (idx < 5 * 256 * 128) {
        int o  = idx & 127;
        int c2 = (idx >> 7) & 255;
        int k  = idx >> 15;
        const float* p = w1 + ((size_t)(k * 512 + 2 * c2)) * 128 + o;
        g_wpk1[idx] = make_float2(p[0], p[128]);
    }
    if (idx < 3 * 64 * 1024) {
        int o  = idx & 1023;
        int c2 = (idx >> 10) & 63;
        int k  = idx >> 16;
        const float* p = w2 + ((size_t)(k * 128 + 2 * c2)) * 1024 + o;
        g_wpk2[idx] = make_float2(p[0], p[1024]);
    }
}

// ---------------------------------------------------------------------------
// Kernel A1: conv1 partials. grid = 5src x 20tg x 8eh = 800 blocks, 256 thr.
// Block: 32 timesteps, E-slice of 64 (single smem stage, 25KB).
// Warp tile: 8 timesteps x (lane: 2 channels); warps = 4 ts-groups x 2 ch-halves.
// Per c2-step: 2 LDG.128 + 8 broadcast LDS.128 per 32 FFMA2 (balanced).
// ---------------------------------------------------------------------------
#define C1TS 32
#define C1ROWS (3 * (C1TS - 1) + 5)   // 98
#define EC 64

__global__ void __launch_bounds__(256) conv1_raw(const float* __restrict__ values,
                                                 const float* __restrict__ symbols) {
    __shared__ float xs[C1ROWS * EC];   // 25KB

    int blk = blockIdx.x;               // (src*20 + tg)*8 + eh
    int eh  = blk & 7;
    int st  = blk >> 3;                 // 0..99
    int src = st / 20;
    int tg  = st % 20;
    int t0  = tg * C1TS;
    const float* x = (src < 4) ? (values + (size_t)src * T_IN * E_IN) : symbols;
    int base_row = t0 * 3 - 1;
    int col0 = eh * EC;

    int t    = threadIdx.x;
    int lane = t & 31;
    int wrp  = t >> 5;                  // 0..7
    int tsg  = wrp & 3;                 // 4 ts-groups
    int chh  = wrp >> 2;                // 2 channel halves
    int ch0  = chh * 64 + lane * 2;
    int ts0  = tsg * 8;                 // 8 timesteps per warp

    // stage 98 rows x 64 cols
    for (int idx = t; idx < C1ROWS * (EC / 4); idx += 256) {
        int r  = idx >> 4;              // EC/4 = 16
        int c4 = idx & 15;
        int gr = base_row + r;
        float4 v = make_float4(0.f, 0.f, 0.f, 0.f);
        if (gr >= 0 && gr < T_IN)
            v = *(const float4*)(x + (size_t)gr * E_IN + col0 + c4 * 4);
        ((float4*)xs)[idx] = v;
    }
    __syncthreads();

    unsigned long long acc[8][2];       // [ts][ch]
#pragma unroll
    for (int j = 0; j < 8; j++) { acc[j][0] = 0ULL; acc[j][1] = 0ULL; }

#pragma unroll
    for (int k = 0; k < 5; k++) {
        const float2* wrow = g_wpk1 + ((size_t)(k * 256 + eh * 32)) * 128 + ch0;
#pragma unroll 2
        for (int c2 = 0; c2 < EC / 2; c2 += 2) {   // pairs c2, c2+1
            ulonglong2 w0 = *(const ulonglong2*)(wrow + (size_t)c2 * 128);        // (ch0,ch0+1) @ c2
            ulonglong2 w1 = *(const ulonglong2*)(wrow + (size_t)(c2 + 1) * 128);  // (ch0,ch0+1) @ c2+1
#pragma unroll
            for (int j = 0; j < 8; j++) {
                ulonglong2 xv = *(const ulonglong2*)&xs[(3 * (ts0 + j) + k) * EC + 2 * c2];
                acc[j][0] = fma2(xv.x, w0.x, acc[j][0]);
                acc[j][1] = fma2(xv.x, w0.y, acc[j][1]);
                acc[j][0] = fma2(xv.y, w1.x, acc[j][0]);
                acc[j][1] = fma2(xv.y, w1.y, acc[j][1]);
            }
        }
    }

    float* outp = g_c1p[eh];
#pragma unroll
    for (int j = 0; j < 8; j++) {
        float2 o2 = make_float2(pksum(acc[j][0]), pksum(acc[j][1]));
        *(float2*)&outp[((size_t)src * T1 + (t0 + ts0 + j)) * C1 + ch0] = o2;
    }
}

// ---------------------------------------------------------------------------
// Kernel A2: sum conv1 partials + bias + layernorm(128) + silu -> g_h1
// 400 blocks x 256 thr; warp = 1 row, lane = 4 channels (warp-local LN).
// ---------------------------------------------------------------------------
__global__ void ln1_silu(const float* __restrict__ bias,
                         const float* __restrict__ lng,
                         const float* __restrict__ lnb) {
    int row  = blockIdx.x * 8 + (threadIdx.x >> 5);   // 0..3199
    int lane = threadIdx.x & 31;
    int ch0  = lane * 4;
    size_t off = (size_t)row * C1 + ch0;

    float4 v = *(const float4*)&bias[ch0];
#pragma unroll
    for (int eh = 0; eh < 8; eh++) {
        float4 p = *(const float4*)&g_c1p[eh][off];
        v.x += p.x; v.y += p.y; v.z += p.z; v.w += p.w;
    }
    float s  = v.x + v.y + v.z + v.w;
    float s2 = v.x * v.x + v.y * v.y + v.z * v.z + v.w * v.w;
#pragma unroll
    for (int o = 16; o; o >>= 1) {
        s  += __shfl_xor_sync(0xffffffffu, s,  o);
        s2 += __shfl_xor_sync(0xffffffffu, s2, o);
    }
    float m   = s * (1.0f / C1);
    float var = s2 * (1.0f / C1) - m * m;
    float rs  = rsqrtf(var + 1e-3f);
    float4 g4 = *(const float4*)&lng[ch0];
    float4 b4 = *(const float4*)&lnb[ch0];
    float4 o4;
    o4.x = silu_f((v.x - m) * rs * g4.x + b4.x);
    o4.y = silu_f((v.y - m) * rs * g4.y + b4.y);
    o4.z = silu_f((v.z - m) * rs * g4.z + b4.z);
    o4.w = silu_f((v.w - m) * rs * g4.w + b4.w);
    *(float4*)&g_h1[off] = o4;
}

// ---------------------------------------------------------------------------
// Kernel B1: conv2 partials per k-tap.
// grid = 40 rowgroups x 4 chq x 3 k = 480 blocks, 256 thr.
// Thread: 1 channel x 16 output rows. Stage 16 input rows (8KB).
// ---------------------------------------------------------------------------
__global__ void __launch_bounds__(256) conv2_raw() {
    __shared__ float xs[16 * C1];   // 8KB

    int blk = blockIdx.x;
    int k   = blk % 3;
    int r1  = blk / 3;              // 0..159
    int chq = r1 & 3;
    int rg  = r1 >> 2;              // 0..39
    int R0  = rg * 16;              // global output row (src*T2 + t2)
    int src = R0 >> 7;
    int t0  = R0 & 127;

    int t  = threadIdx.x;
    int ch = chq * 256 + t;

    // stage 16 input rows: g_h1 row = src*T1 + 5*(t0+j) + k
    for (int idx = t; idx < 16 * (C1 / 4); idx += 256) {
        int r = idx >> 5, c4 = idx & 31;
        const float* src_row = g_h1 + ((size_t)src * T1 + 5 * (t0 + r) + k) * C1;
        ((float4*)xs)[idx] = *(const float4*)(src_row + c4 * 4);
    }
    __syncthreads();

    unsigned long long acc[16];
#pragma unroll
    for (int j = 0; j < 16; j++) acc[j] = 0ULL;

    const float2* wrow = g_wpk2 + (size_t)(k * 64) * 1024 + ch;
#pragma unroll 2
    for (int c2 = 0; c2 < 64; c2 += 2) {
        unsigned long long wa = *(const unsigned long long*)(wrow + (size_t)c2 * 1024);
        unsigned long long wb = *(const unsigned long long*)(wrow + (size_t)(c2 + 1) * 1024);
#pragma unroll
        for (int j = 0; j < 16; j++) {
            ulonglong2 xv = *(const ulonglong2*)&xs[j * C1 + 2 * c2];
            acc[j] = fma2(xv.x, wa, acc[j]);
            acc[j] = fma2(xv.y, wb, acc[j]);
        }
    }

    float* outp = g_c2p[k];
#pragma unroll
    for (int j = 0; j < 16; j++)
        outp[(size_t)(R0 + j) * C2 + ch] = pksum(acc[j]);
}

// ---------------------------------------------------------------------------
// Kernel B2: sum conv2 partials + bias + layernorm(1024) + silu
// 640 blocks x 256 thr.
// ---------------------------------------------------------------------------
__global__ void ln2_silu(const float* __restrict__ bias,
                         const float* __restrict__ lng,
                         const float* __restrict__ lnb,
                         float* __restrict__ out_vp_copy) {
    __shared__ float red[2][8];
    int row = blockIdx.x;
    int src = row >> 7;
    int t = threadIdx.x, lane = t & 31, wid = t >> 5;
    int ch = 4 * t;
    size_t off = (size_t)row * C2 + ch;

    float4 v = *(const float4*)&bias[ch];
#pragma unroll
    for (int k = 0; k < 3; k++) {
        float4 p = *(const float4*)&g_c2p[k][off];
        v.x += p.x; v.y += p.y; v.z += p.z; v.w += p.w;
    }
    float s  = v.x + v.y + v.z + v.w;
    float s2 = v.x * v.x + v.y * v.y + v.z * v.z + v.w * v.w;
#pragma unroll
    for (int o = 16; o; o >>= 1) {
        s  += __shfl_xor_sync(0xffffffffu, s,  o);
        s2 += __shfl_xor_sync(0xffffffffu, s2, o);
    }
    if (lane == 0) { red[0][wid] = s; red[1][wid] = s2; }
    __syncthreads();
    float sum = 0.f, sumsq = 0.f;
#pragma unroll
    for (int q = 0; q < 8; q++) { sum += red[0][q]; sumsq += red[1][q]; }
    float m   = sum * (1.0f / C2);
    float var = sumsq * (1.0f / C2) - m * m;
    float rs  = rsqrtf(var + 1e-3f);

    float4 g4 = *(const float4*)&lng[ch];
    float4 b4 = *(const float4*)&lnb[ch];
    float4 o4;
    o4.x = silu_f((v.x - m) * rs * g4.x + b4.x);
    o4.y = silu_f((v.y - m) * rs * g4.y + b4.y);
    o4.z = silu_f((v.z - m) * rs * g4.z + b4.z);
    o4.w = silu_f((v.w - m) * rs * g4.w + b4.w);

    if (src < 4) {
        *(float4*)&g_vp[off] = o4;
        *(float4*)&out_vp_copy[off] = o4;
    } else {
        *(float4*)&g_sp[(size_t)(row - 4 * T2) * C2 + ch] = o4;
    }
}

// ---------------------------------------------------------------------------
// Kernel C: similarity partials per 128-d chunk.
// 512 blocks (dc8, b4, jt4, it4) x 256 thr; 32x32 tile, 2x2 per thread
// with ti/ti+16 mapping (2-way instead of 4-way smem conflicts).
// ---------------------------------------------------------------------------
__device__ __forceinline__ float sgnx(float a, float s) {
    float b = a + s;
    unsigned int x = (__float_as_uint(a) ^ __float_as_uint(b));
    return __uint_as_float((x & 0x80000000u) | 0x3f800000u);
}

__global__ void sim_kernel() {
    __shared__ float vps[32][132];
    __shared__ float sps[32][132];

    int blk = blockIdx.x;
    int dc = blk >> 6;
    int b  = (blk >> 4) & 3;
    int jt = (blk >> 2) & 3;
    int it = blk & 3;
    int i0 = it * 32, j0 = jt * 32;
    int d0 = dc * 128;
    int t  = threadIdx.x;
    int ti = t & 15;
    int tj = t >> 4;

    for (int e = t; e < 32 * 32; e += 256) {
        int r = e >> 5, c4 = e & 31;
        *(float4*)&vps[r][c4 * 4] =
            *(const float4*)&g_vp[((size_t)(b * T2 + i0 + r)) * C2 + d0 + c4 * 4];
        *(float4*)&sps[r][c4 * 4] =
            *(const float4*)&g_sp[(size_t)(j0 + r) * C2 + d0 + c4 * 4];
    }
    __syncthreads();

    float a00 = 0.f, a01 = 0.f, a10 = 0.f, a11 = 0.f;
#pragma unroll 4
    for (int c4 = 0; c4 < 32; c4++) {
        float4 v0 = *(const float4*)&vps[ti][c4 * 4];
        float4 v1 = *(const float4*)&vps[ti + 16][c4 * 4];
        float4 s0 = *(const float4*)&sps[tj][c4 * 4];
        float4 s1 = *(const float4*)&sps[tj + 16][c4 * 4];
        a00 += sgnx(v0.x, s0.x) + sgnx(v0.y, s0.y) + sgnx(v0.z, s0.z) + sgnx(v0.w, s0.w);
        a01 += sgnx(v0.x, s1.x) + sgnx(v0.y, s1.y) + sgnx(v0.z, s1.z) + sgnx(v0.w, s1.w);
        a10 += sgnx(v1.x, s0.x) + sgnx(v1.y, s0.y) + sgnx(v1.z, s0.z) + sgnx(v1.w, s0.w);
        a11 += sgnx(v1.x, s1.x) + sgnx(v1.y, s1.y) + sgnx(v1.z, s1.z) + sgnx(v1.w, s1.w);
    }

    float* Sp = g_S8[dc] + (size_t)b * T2 * T2;
    Sp[(size_t)(j0 + tj) * T2 + (i0 + ti)]            = a00;
    Sp[(size_t)(j0 + tj) * T2 + (i0 + ti + 16)]       = a10;
    Sp[(size_t)(j0 + tj + 16) * T2 + (i0 + ti)]       = a01;
    Sp[(size_t)(j0 + tj + 16) * T2 + (i0 + ti + 16)]  = a11;
}

// ---------------------------------------------------------------------------
// Kernel D: softmax (summing S8 partials) + scores @ vp + silu(attn * sp)
// 512 blocks (b4, jg16 of 8 rows, dq8 of 128 d) x 128 thr (1 float each).
// ---------------------------------------------------------------------------
__global__ void attn_kernel(float* __restrict__ out) {
    __shared__ float sc[8][T2];

    int blk = blockIdx.x;
    int b  = blk >> 7;
    int jg = (blk >> 3) & 15;
    int dq = blk & 7;
    int j0 = jg * 8;
    int d0 = dq * 128;

    int t = threadIdx.x, lane = t & 31, wrp = t >> 5;

#pragma unroll
    for (int rr = 0; rr < 2; rr++) {       // 4 warps x 2 rows
        int j = j0 + wrp * 2 + rr;
        float v[4];
#pragma unroll
        for (int u = 0; u < 4; u++) {
            float s = 0.f;
#pragma unroll
            for (int dc = 0; dc < 8; dc++)
                s += g_S8[dc][((size_t)b * T2 + j) * T2 + lane + 32 * u];
            v[u] = s * (1.0f / 1024.0f);
        }
        float mx = fmaxf(fmaxf(v[0], v[1]), fmaxf(v[2], v[3]));
#pragma unroll
        for (int o = 16; o; o >>= 1)
            mx = fmaxf(mx, __shfl_xor_sync(0xffffffffu, mx, o));
        float sum = 0.f;
#pragma unroll
        for (int u = 0; u < 4; u++) { v[u] = expf(v[u] - mx); sum += v[u]; }
#pragma unroll
        for (int o = 16; o; o >>= 1)
            sum += __shfl_xor_sync(0xffffffffu, sum, o);
        float invs = 1.0f / sum;
#pragma unroll
        for (int u = 0; u < 4; u++) sc[wrp * 2 + rr][lane + 32 * u] = v[u] * invs;
    }
    __syncthreads();

    int d = d0 + t;
    float acc[8];
#pragma unroll
    for (int jl = 0; jl < 8; jl++) acc[jl] = 0.f;

    const float* vpb = g_vp + (size_t)b * T2 * C2 + d;
#pragma unroll 8
    for (int i = 0; i < T2; i++) {
        float v = vpb[(size_t)i * C2];
#pragma unroll
        for (int jl = 0; jl < 8; jl++)
            acc[jl] += sc[jl][i] * v;
    }

#pragma unroll
    for (int jl = 0; jl < 8; jl++) {
        int j = j0 + jl;
        float spv = g_sp[(size_t)j * C2 + d];
        out[((size_t)(b * T2 + j)) * C2 + d] = silu_f(acc[jl] * spv);
    }
}

// ---------------------------------------------------------------------------
extern "C" void kernel_launch(void* const* d_in, const int* in_sizes, int n_in,
                              void* d_out, int out_size) {
    const float* values  = (const float*)d_in[0];
    const float* symbols = (const float*)d_in[1];
    const float* c1w     = (const float*)d_in[2];
    const float* c1b     = (const float*)d_in[3];
    const float* l1g     = (const float*)d_in[4];
    const float* l1b     = (const float*)d_in[5];
    const float* c2w     = (const float*)d_in[6];
    const float* c2b     = (const float*)d_in[7];
    const float* l2g     = (const float*)d_in[8];
    const float* l2b     = (const float*)d_in[9];
    float* out = (float*)d_out;
    float* out_vp = out + (size_t)BATCH * T2 * C2;

    prepack<<<768, 256>>>(c1w, c2w);
    conv1_raw<<<800, 256>>>(values, symbols);
    ln1_silu<<<400, 256>>>(c1b, l1g, l1b);
    conv2_raw<<<480, 256>>>();
    ln2_silu<<<640, 256>>>(c2b, l2g, l2b, out_vp);
    sim_kernel<<<512, 256>>>();
    attn_kernel<<<512, 128>>>(out);
}